// round 3
// baseline (speedup 1.0000x reference)
#include <cuda_runtime.h>

typedef unsigned long long u64;

__device__ __forceinline__ u64 pk2(float lo, float hi) {
    u64 r;
    asm("mov.b64 %0, {%1, %2};" : "=l"(r)
        : "r"(__float_as_uint(lo)), "r"(__float_as_uint(hi)));
    return r;
}
__device__ __forceinline__ u64 ffma2(u64 a, u64 b, u64 c) {
    u64 d;
    asm("fma.rn.f32x2 %0, %1, %2, %3;" : "=l"(d) : "l"(a), "l"(b), "l"(c));
    return d;
}
__device__ __forceinline__ float f2lo(u64 v) { return __uint_as_float((unsigned)v); }
__device__ __forceinline__ float f2hi(u64 v) { return __uint_as_float((unsigned)(v >> 32)); }

// x: [B,1,7,7,7,7]  w1:[2,1,3,3,3,3] b1:[2]  w2:[4,2,3,3,3,3] b2:[4]
// out: [B, 4*81]
__global__ __launch_bounds__(64)
void fused4d_kernel(const float* __restrict__ x,
                    const float* __restrict__ w1, const float* __restrict__ b1,
                    const float* __restrict__ w2, const float* __restrict__ b2,
                    float* __restrict__ out, int nsamp)
{
    __shared__ __align__(16) float xs[2][2401];
    __shared__ __align__(16) float h1s[2][1250];   // [s][c][5,5,5,5]
    __shared__ float2 w1p[81];        // (oc0,oc1) per tap
    __shared__ float2 w2p[4][81];     // per oc: (ic0,ic1) per tap
    __shared__ float2 b1p;
    __shared__ float  b2s[4];

    const int t  = threadIdx.x;
    const int s0 = blockIdx.x * 2;

    // ---- weights -> smem ----
    for (int i = t; i < 81; i += 64)
        w1p[i] = make_float2(w1[i], w1[81 + i]);
    for (int i = t; i < 324; i += 64) {
        int oc = i / 81, tap = i - oc * 81;
        w2p[oc][tap] = make_float2(w2[oc * 162 + tap], w2[oc * 162 + 81 + tap]);
    }
    if (t == 0) b1p = make_float2(b1[0], b1[1]);
    if (t < 4)  b2s[t] = b2[t];

    // ---- input -> smem (float2-vectorized; 2 samples = 2401 float2) ----
    {
        int nsm = nsamp - s0; if (nsm > 2) nsm = 2;
        if (nsm == 2) {
            const float2* xb = (const float2*)(x + (size_t)s0 * 2401);
            float2* xd = (float2*)&xs[0][0];
            for (int i = t; i < 2401; i += 64) xd[i] = xb[i];
        } else if (nsm == 1) {
            const float* xb = x + (size_t)s0 * 2401;
            for (int i = t; i < 2401; i += 64) xs[0][i] = xb[i];
        }
    }
    __syncthreads();

    // ================= layer 1 =================
    // 25 threads/sample: thread = (l,d); computes all 5x5 (h,w) outputs,
    // both channels packed (oc0,oc1) in f32x2.
    if (t < 50 && s0 + t / 25 < nsamp) {
        const int s   = t / 25;
        const int tid = t % 25;
        const int l   = tid / 5, d = tid % 5;

        const float* xb = &xs[s][0] + l * 343 + d * 49;
        const u64 bb = *(const u64*)&b1p;
        u64 acc[5][5];                       // [h][w]
        #pragma unroll
        for (int h = 0; h < 5; h++)
            #pragma unroll
            for (int p = 0; p < 5; p++) acc[h][p] = bb;

        #pragma unroll
        for (int i = 0; i < 3; i++)
        #pragma unroll
        for (int j = 0; j < 3; j++) {
            const float* pb = xb + i * 343 + j * 49;
            u64 wr[9];
            const u64* wp = (const u64*)&w1p[(i * 3 + j) * 9];
            #pragma unroll
            for (int q = 0; q < 9; q++) wr[q] = wp[q];

            #pragma unroll
            for (int r = 0; r < 7; r++) {
                const float* rp = pb + r * 7;
                u64 xx[7];
                #pragma unroll
                for (int q = 0; q < 7; q++) { float v = rp[q]; xx[q] = pk2(v, v); }
                #pragma unroll
                for (int k = 0; k < 3; k++) {
                    const int h = r - k;
                    if (h >= 0 && h <= 4) {
                        #pragma unroll
                        for (int m = 0; m < 3; m++) {
                            const u64 w = wr[k * 3 + m];
                            #pragma unroll
                            for (int p = 0; p < 5; p++)
                                acc[h][p] = ffma2(xx[p + m], w, acc[h][p]);
                        }
                    }
                }
            }
        }

        float* hb = &h1s[s][0] + l * 125 + d * 25;
        #pragma unroll
        for (int h = 0; h < 5; h++)
            #pragma unroll
            for (int p = 0; p < 5; p++) {
                hb[h * 5 + p]       = fmaxf(f2lo(acc[h][p]), 0.f);
                hb[625 + h * 5 + p] = fmaxf(f2hi(acc[h][p]), 0.f);
            }
    }
    __syncthreads();

    // ================= layer 2 =================
    // 18 threads/sample: thread = (l,d,ocpair); computes 3x3 (h,w) x 2 oc.
    // f32x2 lanes = (ic0,ic1) partials, summed at epilogue.
    if (t < 36 && s0 + t / 18 < nsamp) {
        const int s   = t / 18;
        const int tid = t % 18;
        const int pos = tid >> 1, ocp = tid & 1;
        const int lo  = pos / 3, dd = pos % 3;
        const int oc0 = 2 * ocp;

        const float* hb = &h1s[s][0] + lo * 125 + dd * 25;

        u64 acc[2][3][3];                    // [oc][h][w]
        #pragma unroll
        for (int c = 0; c < 2; c++) {
            u64 ini = pk2(b2s[oc0 + c], 0.f);
            #pragma unroll
            for (int h = 0; h < 3; h++)
                #pragma unroll
                for (int p = 0; p < 3; p++) acc[c][h][p] = ini;
        }

        #pragma unroll
        for (int i = 0; i < 3; i++)
        #pragma unroll
        for (int j = 0; j < 3; j++) {
            const float* pb = hb + i * 125 + j * 25;
            u64 wr[2][9];
            #pragma unroll
            for (int c = 0; c < 2; c++) {
                const u64* wp = (const u64*)&w2p[oc0 + c][(i * 3 + j) * 9];
                #pragma unroll
                for (int q = 0; q < 9; q++) wr[c][q] = wp[q];
            }

            #pragma unroll
            for (int r = 0; r < 5; r++) {
                u64 hh[5];
                #pragma unroll
                for (int q = 0; q < 5; q++)
                    hh[q] = pk2(pb[r * 5 + q], pb[625 + r * 5 + q]);
                #pragma unroll
                for (int k = 0; k < 3; k++) {
                    const int h = r - k;
                    if (h >= 0 && h <= 2) {
                        #pragma unroll
                        for (int m = 0; m < 3; m++)
                        #pragma unroll
                        for (int c = 0; c < 2; c++) {
                            const u64 w = wr[c][k * 3 + m];
                            #pragma unroll
                            for (int p = 0; p < 3; p++)
                                acc[c][h][p] = ffma2(hh[p + m], w, acc[c][h][p]);
                        }
                    }
                }
            }
        }

        float* ob = out + (size_t)(s0 + s) * 324;
        #pragma unroll
        for (int c = 0; c < 2; c++)
            #pragma unroll
            for (int h = 0; h < 3; h++)
                #pragma unroll
                for (int p = 0; p < 3; p++)
                    ob[(oc0 + c) * 81 + lo * 27 + dd * 9 + h * 3 + p] =
                        fmaxf(f2lo(acc[c][h][p]) + f2hi(acc[c][h][p]), 0.f);
    }
}

extern "C" void kernel_launch(void* const* d_in, const int* in_sizes, int n_in,
                              void* d_out, int out_size) {
    const float* x  = (const float*)d_in[0];
    const float* w1 = (const float*)d_in[1];
    const float* b1 = (const float*)d_in[2];
    const float* w2 = (const float*)d_in[3];
    const float* b2 = (const float*)d_in[4];
    float* out = (float*)d_out;

    const int n = in_sizes[0] / 2401;        // B
    const int blocks = (n + 1) / 2;          // 2 samples / 64-thread block
    fused4d_kernel<<<blocks, 64>>>(x, w1, b1, w2, b2, out, n);
}